// round 16
// baseline (speedup 1.0000x reference)
#include <cuda_runtime.h>
#include <cuda_bf16.h>
#include <cuda_fp16.h>
#include <math.h>
#include <float.h>
#include <stdint.h>

#define Nn 50000
#define Ee 800000
#define Hh 4
#define Dd 128
#define HDim 512
#define NEG_ATTN 0.2f
#define NEG_ACT 0.01f

// ---------------- scratch (static device allocations) ----------------
__device__ __half g_feath[(size_t)Nn * HDim];   // fp16 feat (gather source)
__device__ __half g_resh [(size_t)Nn * HDim];   // fp16 res / h (GEMM2 A operand)
__device__ __half g_xh   [(size_t)Nn * Dd];     // layer input x, fp16
__device__ float g_el  [Nn * Hh];
__device__ float g_er  [Nn * Hh];
__device__ int   g_deg [Nn];
__device__ int   g_off [Nn + 1];
__device__ int   g_cur [Nn];
__device__ int   g_csr_src[Ee];
__device__ int   g_btot[128];
__device__ int   g_boff[128];

// transposed weights, [n][k] layout
__device__ __half g_w1h[4u * 1024 * 128];          // plain fp16 for GEMM1
__device__ __half g_w2h[4u * 128 * 512];           // fp16 hi/lo for GEMM2
__device__ __half g_w2l[4u * 128 * 512];

// smem offsets (bytes): tiles of [128][72] 16-bit = 18432 each
#define O_BHIo 18432
#define O_BLOo 36864
#define SMEM_G1 36864
#define O2_PAR 55296
#define SMEM_G2 (55296 + 1536)

// ---------------- helpers ----------------
__device__ __forceinline__ uint32_t s2u(const void* p) {
    uint32_t a;
    asm("{ .reg .u64 t; cvta.to.shared.u64 t, %1; cvt.u32.u64 %0, t; }" : "=r"(a) : "l"(p));
    return a;
}

#define LDSM4(R, A) \
    asm volatile("ldmatrix.sync.aligned.m8n8.x4.shared.b16 {%0,%1,%2,%3}, [%4];" \
        : "=r"((R)[0]), "=r"((R)[1]), "=r"((R)[2]), "=r"((R)[3]) : "r"(A))

__device__ __forceinline__ void mma_f16(float d[4], const uint32_t a[4],
                                        uint32_t b0, uint32_t b1) {
    asm volatile(
        "mma.sync.aligned.m16n8k16.row.col.f32.f16.f16.f32 "
        "{%0,%1,%2,%3},{%4,%5,%6,%7},{%8,%9},{%0,%1,%2,%3};"
        : "+f"(d[0]), "+f"(d[1]), "+f"(d[2]), "+f"(d[3])
        : "r"(a[0]), "r"(a[1]), "r"(a[2]), "r"(a[3]), "r"(b0), "r"(b1));
}

// ---------------- weight / input prep ----------------
__global__ void k_prep_w1(const float* __restrict__ Wfc, const float* __restrict__ Wres) {
    int id = blockIdx.x * 256 + threadIdx.x;
    if (id >= 4 * 1024 * 128) return;
    int k = id & 127, n = (id >> 7) & 1023, l = id >> 17;
    float v = (n < 512) ? Wfc[((size_t)l * 128 + k) * 512 + n]
                        : Wres[((size_t)l * 128 + k) * 512 + (n - 512)];
    g_w1h[id] = __float2half_rn(v);
}

__global__ void k_prep_w2(const float* __restrict__ Wn) {
    int id = blockIdx.x * 256 + threadIdx.x;
    if (id >= 4 * 128 * 512) return;
    int k = id & 511, n = (id >> 9) & 127, l = id >> 16;
    float v = Wn[((size_t)l * 512 + k) * 128 + n];
    __half h = __float2half_rn(v);
    g_w2h[id] = h;
    g_w2l[id] = __float2half_rn(v - __half2float(h));
}

__global__ void k_prep_x(const float* __restrict__ X) {
    int id = blockIdx.x * 256 + threadIdx.x;
    if (id >= Nn * Dd) return;
    g_xh[id] = __float2half_rn(X[id]);
}

// ---------------- CSR build ----------------
__global__ void k_zero_deg() {
    int i = blockIdx.x * blockDim.x + threadIdx.x;
    if (i < Nn) g_deg[i] = 0;
}
__global__ void k_hist(const int* __restrict__ dst) {
    int i = blockIdx.x * blockDim.x + threadIdx.x;
    if (i < Ee) atomicAdd(&g_deg[dst[i]], 1);
}
// 3-phase scan: per-block local scan -> scan of 98 block totals -> add offsets
__global__ void k_scan1() {          // grid 98, block 512
    __shared__ int sb[512];
    int b = blockIdx.x, t = threadIdx.x;
    int i = b * 512 + t;
    int v = (i < Nn) ? g_deg[i] : 0;
    sb[t] = v;
    __syncthreads();
    for (int off = 1; off < 512; off <<= 1) {
        int a = (t >= off) ? sb[t - off] : 0;
        __syncthreads();
        sb[t] += a;
        __syncthreads();
    }
    if (i < Nn) g_off[i] = sb[t] - v;      // exclusive within block
    if (t == 511) g_btot[b] = sb[511];
}
__global__ void k_scan2() {          // 1 block, 128 threads
    __shared__ int sb[128];
    int t = threadIdx.x;
    int v = (t < 98) ? g_btot[t] : 0;
    sb[t] = v;
    __syncthreads();
    for (int off = 1; off < 128; off <<= 1) {
        int a = (t >= off) ? sb[t - off] : 0;
        __syncthreads();
        sb[t] += a;
        __syncthreads();
    }
    g_boff[t] = sb[t] - v;
    if (t == 127) g_off[Nn] = sb[127];     // grand total
}
__global__ void k_scan3() {          // grid 196, block 256
    int i = blockIdx.x * 256 + threadIdx.x;
    if (i < Nn) {
        int o = g_off[i] + g_boff[i >> 9];
        g_off[i] = o;
        g_cur[i] = o;
    }
}
__global__ void k_scatter(const int* __restrict__ src, const int* __restrict__ dst) {
    int i = blockIdx.x * blockDim.x + threadIdx.x;
    if (i < Ee) {
        int d = dst[i];
        int p = atomicAdd(&g_cur[d], 1);
        g_csr_src[p] = src[i];
    }
}

// ============ GEMM1: [feat|res] = x(fp16) @ W1(fp16) ; fused el/er for yb<4 ============
__global__ void __launch_bounds__(256) k_gemm1(int l, const float* __restrict__ al,
                                               const float* __restrict__ ar) {
    extern __shared__ char smem[];
    uint32_t sb = s2u(smem);
    int t = threadIdx.x, lane = t & 31, wid = t >> 5;
    int gr = lane >> 2, gc = lane & 3;
    int wm = (wid & 1) * 64, wnid = wid >> 1, wn = wnid * 32;
    int row0 = blockIdx.x * 128;
    int yb = blockIdx.y;

    const __half* Wh = g_w1h + ((size_t)l * 1024 + (size_t)yb * 128) * 128;

    float d[4][4][4];
#pragma unroll
    for (int i = 0; i < 4; i++)
#pragma unroll
        for (int j = 0; j < 4; j++)
#pragma unroll
            for (int q = 0; q < 4; q++) d[i][j][q] = 0.f;

    int arow = (lane & 7) + ((lane >> 3) & 1) * 8;
    int akof = (lane >> 4) * 8;
    int bnr  = (lane & 7) + ((lane >> 4) << 3);
    int bkof = ((lane >> 3) & 1) * 8;

#pragma unroll
    for (int kc = 0; kc < 2; kc++) {
        int k0 = kc * 64;
#pragma unroll
        for (int u = 0; u < 4; u++) {
            int id = t + 256 * u;
            int r = id >> 3, c8 = (id & 7) * 8;
            int grow = row0 + r;
            uint4 v = make_uint4(0u, 0u, 0u, 0u);
            if (grow < Nn) v = *reinterpret_cast<const uint4*>(g_xh + (size_t)grow * Dd + k0 + c8);
            *reinterpret_cast<uint4*>(smem + (size_t)(r * 72 + c8) * 2) = v;
        }
#pragma unroll
        for (int u = 0; u < 4; u++) {
            int id = t + 256 * u;
            int r = id >> 3, c8 = (id & 7) * 8;
            *reinterpret_cast<uint4*>(smem + O_BHIo + (size_t)(r * 72 + c8) * 2) =
                *reinterpret_cast<const uint4*>(Wh + (size_t)r * 128 + k0 + c8);
        }
        __syncthreads();
#pragma unroll
        for (int kt = 0; kt < 4; kt++) {
            uint32_t ah[4][4], bhf[2][4];
#pragma unroll
            for (int mt = 0; mt < 4; mt++) {
                uint32_t ad = sb + 2u * ((wm + 16 * mt + arow) * 72 + 16 * kt + akof);
                LDSM4(ah[mt], ad);
            }
#pragma unroll
            for (int g = 0; g < 2; g++) {
                uint32_t bd = sb + O_BHIo + 2u * ((wn + 16 * g + bnr) * 72 + 16 * kt + bkof);
                LDSM4(bhf[g], bd);
            }
#pragma unroll
            for (int mt = 0; mt < 4; mt++)
#pragma unroll
                for (int nt = 0; nt < 4; nt++) {
                    uint32_t bh0 = bhf[nt >> 1][(nt & 1) * 2], bh1 = bhf[nt >> 1][(nt & 1) * 2 + 1];
                    mma_f16(d[mt][nt], ah[mt], bh0, bh1);
                }
        }
        __syncthreads();
    }

    // fp16 store (feat for yb<4, res for yb>=4)
    __half* C = (yb < 4) ? g_feath : g_resh;
    int wc0 = (yb & 3) * 128;
#pragma unroll
    for (int mt = 0; mt < 4; mt++) {
        int r0 = row0 + wm + 16 * mt + gr;
        int r1 = r0 + 8;
#pragma unroll
        for (int nt = 0; nt < 4; nt++) {
            int col = wc0 + wn + nt * 8 + 2 * gc;
            if (r0 < Nn)
                *reinterpret_cast<__half2*>(C + (size_t)r0 * HDim + col) =
                    __floats2half2_rn(d[mt][nt][0], d[mt][nt][1]);
            if (r1 < Nn)
                *reinterpret_cast<__half2*>(C + (size_t)r1 * HDim + col) =
                    __floats2half2_rn(d[mt][nt][2], d[mt][nt][3]);
        }
    }

    // fused el/er for this block's head (yb<4): fp32 dot from accumulators
    if (yb < 4) {
        float* red_el = reinterpret_cast<float*>(smem);
        float* red_er = reinterpret_cast<float*>(smem + 2048);
        float alv[4][2], arv[4][2];
#pragma unroll
        for (int nt = 0; nt < 4; nt++) {
            int dim = wn + nt * 8 + 2 * gc;
            alv[nt][0] = al[yb * 128 + dim];     alv[nt][1] = al[yb * 128 + dim + 1];
            arv[nt][0] = ar[yb * 128 + dim];     arv[nt][1] = ar[yb * 128 + dim + 1];
        }
#pragma unroll
        for (int mt = 0; mt < 4; mt++) {
            float sl0 = 0.f, sr0 = 0.f, sl1 = 0.f, sr1 = 0.f;
#pragma unroll
            for (int nt = 0; nt < 4; nt++) {
                sl0 += d[mt][nt][0] * alv[nt][0] + d[mt][nt][1] * alv[nt][1];
                sr0 += d[mt][nt][0] * arv[nt][0] + d[mt][nt][1] * arv[nt][1];
                sl1 += d[mt][nt][2] * alv[nt][0] + d[mt][nt][3] * alv[nt][1];
                sr1 += d[mt][nt][2] * arv[nt][0] + d[mt][nt][3] * arv[nt][1];
            }
#pragma unroll
            for (int o = 1; o < 4; o <<= 1) {
                sl0 += __shfl_xor_sync(0xffffffffu, sl0, o);
                sr0 += __shfl_xor_sync(0xffffffffu, sr0, o);
                sl1 += __shfl_xor_sync(0xffffffffu, sl1, o);
                sr1 += __shfl_xor_sync(0xffffffffu, sr1, o);
            }
            if (gc == 0) {
                int rb = wm + 16 * mt + gr;
                red_el[wnid * 128 + rb] = sl0;      red_el[wnid * 128 + rb + 8] = sl1;
                red_er[wnid * 128 + rb] = sr0;      red_er[wnid * 128 + rb + 8] = sr1;
            }
        }
        __syncthreads();
        if (gc == 0 && wnid == 0) {
#pragma unroll
            for (int mt = 0; mt < 4; mt++) {
                int rb = wm + 16 * mt + gr;
#pragma unroll
                for (int q = 0; q < 2; q++) {
                    int rr = rb + 8 * q;
                    int node = row0 + rr;
                    if (node < Nn) {
                        float e = red_el[rr] + red_el[128 + rr] + red_el[256 + rr] + red_el[384 + rr];
                        float f = red_er[rr] + red_er[128 + rr] + red_er[256 + rr] + red_er[384 + rr];
                        g_el[node * 4 + yb] = e;
                        g_er[node * 4 + yb] = f;
                    }
                }
            }
        }
    }
}

// ============ GEMM2 + bias + LayerNorm: out = LN(h(fp16) @ Wn + bn) ============
__global__ void __launch_bounds__(256) k_gemm2(int l, const float* __restrict__ bn,
                                               const float* __restrict__ gam,
                                               const float* __restrict__ bet,
                                               float* __restrict__ out, int last) {
    extern __shared__ char smem[];
    uint32_t sb = s2u(smem);
    int t = threadIdx.x, lane = t & 31, wid = t >> 5;
    int gr = lane >> 2, gc = lane & 3;
    int wm = (wid & 1) * 64, wnid = wid >> 1, wn = wnid * 32;
    int row0 = blockIdx.x * 128;

    float* par = reinterpret_cast<float*>(smem + O2_PAR);
    if (t < 128) { par[t] = bn[t]; par[128 + t] = gam[t]; par[256 + t] = bet[t]; }

    const __half* Wh = g_w2h + (size_t)l * 128 * 512;
    const __half* Wl = g_w2l + (size_t)l * 128 * 512;

    float d[4][4][4];
#pragma unroll
    for (int i = 0; i < 4; i++)
#pragma unroll
        for (int j = 0; j < 4; j++)
#pragma unroll
            for (int q = 0; q < 4; q++) d[i][j][q] = 0.f;

    int arow = (lane & 7) + ((lane >> 3) & 1) * 8;
    int akof = (lane >> 4) * 8;
    int bnr  = (lane & 7) + ((lane >> 4) << 3);
    int bkof = ((lane >> 3) & 1) * 8;

    for (int kc = 0; kc < 8; kc++) {
        int k0 = kc * 64;
#pragma unroll
        for (int u = 0; u < 4; u++) {
            int id = t + 256 * u;
            int r = id >> 3, c8 = (id & 7) * 8;
            int grow = row0 + r;
            uint4 v = make_uint4(0u, 0u, 0u, 0u);
            if (grow < Nn) v = *reinterpret_cast<const uint4*>(g_resh + (size_t)grow * HDim + k0 + c8);
            *reinterpret_cast<uint4*>(smem + (size_t)(r * 72 + c8) * 2) = v;
        }
#pragma unroll
        for (int u = 0; u < 4; u++) {
            int id = t + 256 * u;
            int r = id >> 3, c8 = (id & 7) * 8;
            char* pb = smem + O_BHIo + (size_t)(r * 72 + c8) * 2;
            *reinterpret_cast<uint4*>(pb) = *reinterpret_cast<const uint4*>(Wh + (size_t)r * 512 + k0 + c8);
            *reinterpret_cast<uint4*>(pb + (O_BLOo - O_BHIo)) = *reinterpret_cast<const uint4*>(Wl + (size_t)r * 512 + k0 + c8);
        }
        __syncthreads();
#pragma unroll
        for (int kt = 0; kt < 4; kt++) {
            uint32_t ah[4][4], bhf[2][4], blf[2][4];
#pragma unroll
            for (int mt = 0; mt < 4; mt++) {
                uint32_t ad = sb + 2u * ((wm + 16 * mt + arow) * 72 + 16 * kt + akof);
                LDSM4(ah[mt], ad);
            }
#pragma unroll
            for (int g = 0; g < 2; g++) {
                uint32_t bd = sb + O_BHIo + 2u * ((wn + 16 * g + bnr) * 72 + 16 * kt + bkof);
                LDSM4(bhf[g], bd);
                LDSM4(blf[g], bd + (O_BLOo - O_BHIo));
            }
#pragma unroll
            for (int mt = 0; mt < 4; mt++)
#pragma unroll
                for (int nt = 0; nt < 4; nt++) {
                    uint32_t bh0 = bhf[nt >> 1][(nt & 1) * 2], bh1 = bhf[nt >> 1][(nt & 1) * 2 + 1];
                    uint32_t bl0 = blf[nt >> 1][(nt & 1) * 2], bl1 = blf[nt >> 1][(nt & 1) * 2 + 1];
                    mma_f16(d[mt][nt], ah[mt], bh0, bh1);
                    mma_f16(d[mt][nt], ah[mt], bl0, bl1);
                }
        }
        __syncthreads();
    }

    // ---- fused bias + LayerNorm epilogue ----
    float* red_s = reinterpret_cast<float*>(smem);
    float* red_q = reinterpret_cast<float*>(smem + 2048);
    float bnv[4][2];
#pragma unroll
    for (int nt = 0; nt < 4; nt++) {
        int col = wn + nt * 8 + 2 * gc;
        bnv[nt][0] = par[col]; bnv[nt][1] = par[col + 1];
    }
#pragma unroll
    for (int mt = 0; mt < 4; mt++) {
        float s0 = 0.f, q0 = 0.f, s1 = 0.f, q1 = 0.f;
#pragma unroll
        for (int nt = 0; nt < 4; nt++) {
            float y00 = d[mt][nt][0] + bnv[nt][0];
            float y01 = d[mt][nt][1] + bnv[nt][1];
            float y10 = d[mt][nt][2] + bnv[nt][0];
            float y11 = d[mt][nt][3] + bnv[nt][1];
            d[mt][nt][0] = y00; d[mt][nt][1] = y01;
            d[mt][nt][2] = y10; d[mt][nt][3] = y11;
            s0 += y00 + y01; q0 += y00 * y00 + y01 * y01;
            s1 += y10 + y11; q1 += y10 * y10 + y11 * y11;
        }
#pragma unroll
        for (int o = 1; o < 4; o <<= 1) {
            s0 += __shfl_xor_sync(0xffffffffu, s0, o);
            q0 += __shfl_xor_sync(0xffffffffu, q0, o);
            s1 += __shfl_xor_sync(0xffffffffu, s1, o);
            q1 += __shfl_xor_sync(0xffffffffu, q1, o);
        }
        if (gc == 0) {
            int rb = wm + 16 * mt + gr;
            red_s[wnid * 128 + rb] = s0; red_q[wnid * 128 + rb] = q0;
            red_s[wnid * 128 + rb + 8] = s1; red_q[wnid * 128 + rb + 8] = q1;
        }
    }
    __syncthreads();
#pragma unroll
    for (int mt = 0; mt < 4; mt++) {
        int rb = wm + 16 * mt + gr;
        float s0 = red_s[rb] + red_s[128 + rb] + red_s[256 + rb] + red_s[384 + rb];
        float q0 = red_q[rb] + red_q[128 + rb] + red_q[256 + rb] + red_q[384 + rb];
        float s1 = red_s[rb + 8] + red_s[128 + rb + 8] + red_s[256 + rb + 8] + red_s[384 + rb + 8];
        float q1 = red_q[rb + 8] + red_q[128 + rb + 8] + red_q[256 + rb + 8] + red_q[384 + rb + 8];
        float mu0 = s0 * (1.f / 128.f);
        float mu1 = s1 * (1.f / 128.f);
        float rstd0 = rsqrtf(q0 * (1.f / 128.f) - mu0 * mu0 + 1e-5f);
        float rstd1 = rsqrtf(q1 * (1.f / 128.f) - mu1 * mu1 + 1e-5f);
        int r0 = row0 + rb, r1 = r0 + 8;
#pragma unroll
        for (int nt = 0; nt < 4; nt++) {
            int col = wn + nt * 8 + 2 * gc;
            float g0 = par[128 + col], g1 = par[128 + col + 1];
            float b0 = par[256 + col], b1 = par[256 + col + 1];
            float v00 = (d[mt][nt][0] - mu0) * rstd0 * g0 + b0;
            float v01 = (d[mt][nt][1] - mu0) * rstd0 * g1 + b1;
            float v10 = (d[mt][nt][2] - mu1) * rstd1 * g0 + b0;
            float v11 = (d[mt][nt][3] - mu1) * rstd1 * g1 + b1;
            if (last) {
                if (r0 < Nn)
                    *reinterpret_cast<float2*>(out + (size_t)r0 * Dd + col) = make_float2(v00, v01);
                if (r1 < Nn)
                    *reinterpret_cast<float2*>(out + (size_t)r1 * Dd + col) = make_float2(v10, v11);
            } else {
                if (r0 < Nn)
                    *reinterpret_cast<__half2*>(g_xh + (size_t)r0 * Dd + col) = __floats2half2_rn(v00, v01);
                if (r1 < Nn)
                    *reinterpret_cast<__half2*>(g_xh + (size_t)r1 * Dd + col) = __floats2half2_rn(v10, v11);
            }
        }
    }
}

// ---------------- fused edge-softmax + aggregation ----------------
// 2 nodes per 256-thread block. Warp w: node = 2*blk + (w>>2), head = w&3.
__global__ void __launch_bounds__(256) k_aggregate(const float* __restrict__ bgat) {
    int w8 = threadIdx.x >> 5, ln = threadIdx.x & 31;
    int dn = blockIdx.x * 2 + (w8 >> 2);
    int w = w8 & 3;
    int s = g_off[dn], en = g_off[dn + 1];
    float erd = g_er[dn * 4 + w];
    float a0 = 0.f, a1 = 0.f, a2 = 0.f, a3 = 0.f, z = 0.f;

    for (int base = s; base < en; base += 32) {
        int cnt = en - base; if (cnt > 32) cnt = 32;
        int idx = (ln < cnt) ? g_csr_src[base + ln] : 0;
        float e = g_el[idx * 4 + w] + erd;
        e = e > 0.f ? e : NEG_ATTN * e;
        float wv = (ln < cnt) ? __expf(e) : 0.f;
#pragma unroll 2
        for (int j = 0; j < cnt; j++) {
            int sn   = __shfl_sync(0xffffffffu, idx, j);
            float wg = __shfl_sync(0xffffffffu, wv, j);
            uint2 u = *reinterpret_cast<const uint2*>(g_feath + (size_t)sn * 512 + w * 128 + 4 * ln);
            float2 f0 = __half22float2(*reinterpret_cast<__half2*>(&u.x));
            float2 f1 = __half22float2(*reinterpret_cast<__half2*>(&u.y));
            a0 = fmaf(wg, f0.x, a0); a1 = fmaf(wg, f0.y, a1);
            a2 = fmaf(wg, f1.x, a2); a3 = fmaf(wg, f1.y, a3);
            z += wg;
        }
    }

    float iz = 1.f / fmaxf(z, 1e-20f);
    int col = w * 128 + 4 * ln;
    size_t o = (size_t)dn * HDim + col;
    uint2 ru = *reinterpret_cast<const uint2*>(g_resh + o);
    float2 r0 = __half22float2(*reinterpret_cast<__half2*>(&ru.x));
    float2 r1 = __half22float2(*reinterpret_cast<__half2*>(&ru.y));
    float4 bg = *reinterpret_cast<const float4*>(bgat + col);
    float v0 = a0 * iz + r0.x + bg.x; v0 = v0 > 0.f ? v0 : NEG_ACT * v0;
    float v1 = a1 * iz + r0.y + bg.y; v1 = v1 > 0.f ? v1 : NEG_ACT * v1;
    float v2 = a2 * iz + r1.x + bg.z; v2 = v2 > 0.f ? v2 : NEG_ACT * v2;
    float v3 = a3 * iz + r1.y + bg.w; v3 = v3 > 0.f ? v3 : NEG_ACT * v3;
    uint2 ou;
    *reinterpret_cast<__half2*>(&ou.x) = __floats2half2_rn(v0, v1);
    *reinterpret_cast<__half2*>(&ou.y) = __floats2half2_rn(v2, v3);
    *reinterpret_cast<uint2*>(g_resh + o) = ou;
}

// ---------------- launch ----------------
extern "C" void kernel_launch(void* const* d_in, const int* in_sizes, int n_in,
                              void* d_out, int out_size) {
    const float* features = (const float*)d_in[0];
    const int*   src      = (const int*)  d_in[1];
    const int*   dst      = (const int*)  d_in[2];
    const float* W_fc     = (const float*)d_in[3];
    const float* attn_l   = (const float*)d_in[4];
    const float* attn_r   = (const float*)d_in[5];
    const float* W_res    = (const float*)d_in[6];
    const float* b_gat    = (const float*)d_in[7];
    const float* W_nrm    = (const float*)d_in[8];
    const float* b_nrm    = (const float*)d_in[9];
    const float* ln_g     = (const float*)d_in[10];
    const float* ln_b     = (const float*)d_in[11];
    float* out = (float*)d_out;

    cudaFuncSetAttribute(k_gemm1, cudaFuncAttributeMaxDynamicSharedMemorySize, SMEM_G1);
    cudaFuncSetAttribute(k_gemm2, cudaFuncAttributeMaxDynamicSharedMemorySize, SMEM_G2);

    k_zero_deg<<<(Nn + 255) / 256, 256>>>();
    k_hist<<<(Ee + 255) / 256, 256>>>(dst);
    k_scan1<<<98, 512>>>();
    k_scan2<<<1, 128>>>();
    k_scan3<<<(Nn + 255) / 256, 256>>>();
    k_scatter<<<(Ee + 255) / 256, 256>>>(src, dst);
    k_prep_w1<<<(4 * 1024 * 128 + 255) / 256, 256>>>(W_fc, W_res);
    k_prep_x<<<(Nn * Dd + 255) / 256, 256>>>(features);

    for (int l = 0; l < 4; l++) {
        const float* al  = attn_l + (size_t)l * Hh * Dd;
        const float* ar  = attn_r + (size_t)l * Hh * Dd;
        const float* bg  = b_gat + (size_t)l * HDim;
        const float* bnp = b_nrm + (size_t)l * Dd;
        const float* gp  = ln_g  + (size_t)l * Dd;
        const float* bp  = ln_b  + (size_t)l * Dd;

        k_gemm1<<<dim3((Nn + 127) / 128, 8), 256, SMEM_G1>>>(l, al, ar);
        if (l == 0) k_prep_w2<<<(4 * 128 * 512 + 255) / 256, 256>>>(W_nrm);
        k_aggregate<<<Nn / 2, 256>>>(bg);
        k_gemm2<<<(Nn + 127) / 128, 256, SMEM_G2>>>(l, bnp, gp, bp, out, l == 3 ? 1 : 0);
    }
}